// round 12
// baseline (speedup 1.0000x reference)
#include <cuda_runtime.h>

// Problem constants
#define NB      768          // N*C
#define NB4     3072         // quarter-tiles
#define HH      62
#define WW      64
#define KCODE   256
#define NPAIR   128
#define CHUNKS_PER_B 1024    // W * Hp / D
#define M_TOTAL (NB * CHUNKS_PER_B)          // 786432
#define QL_ELEMS (NB * HH * WW)              // 3047424
#define OFF_MSE   QL_ELEMS
#define OFF_INDS  (QL_ELEMS + 1)
#define OFF_RATE  (OFF_INDS + M_TOTAL)
#define OFF_PRIOR (OFF_RATE + 1)
#define OFF_PARAM (OFF_RATE + 2)
#define MSE_COUNT 3145728.0f                 // NB * 1024 * 4

#define NEG_INV_LN2 (-1.4426950408889634f)
#define INV_LMBDA   100.0f

typedef unsigned long long u64;

// Packed codebook, SoA: per pair p, lane-packed {codeword 2p, codeword 2p+1}
struct PK {
    u64 n0[NPAIR];    // {-2*c[2p].x, -2*c[2p+1].x}
    u64 n1[NPAIR];
    u64 n2[NPAIR];
    u64 n3[NPAIR];
    u64 bias[NPAIR];  // {||c||^2 + rate/lambda} per lane
};
__constant__ PK c_pk;        // read via uniform/constant port in the hot loop
__device__   PK g_pk;        // staging buffer written by prep kernel

// Deterministic per-tile partials + completion counter
__device__ float g_pmse[NB4];
__device__ float g_prate[NB4];
__device__ int   g_count;    // zero-init; last block resets it -> graph-replayable

__device__ __forceinline__ u64 pack2(float lo, float hi) {
    u64 r; asm("mov.b64 %0,{%1,%2};" : "=l"(r) : "f"(lo), "f"(hi)); return r;
}
__device__ __forceinline__ void unpack2(u64 v, float& lo, float& hi) {
    asm("mov.b64 {%0,%1},%2;" : "=f"(lo), "=f"(hi) : "l"(v));
}
// packed dual-fp32 FMA (Blackwell f32x2 pipe; 2 MACs per issue slot)
__device__ __forceinline__ u64 fma2(u64 a, u64 b, u64 c) {
    u64 d; asm("fma.rn.f32x2 %0,%1,%2,%3;" : "=l"(d) : "l"(a), "l"(b), "l"(c)); return d;
}

// ---- prep: pack codebook into staging buffer (then D2D memcpy -> __constant__) ----
__global__ __launch_bounds__(NPAIR)
void vq_prep(const float* __restrict__ cb, const float* __restrict__ lpmf)
{
    const int p = threadIdx.x;           // 0..127
    float4 c0 = *(const float4*)(cb + (2 * p) * 4);
    float4 c1 = *(const float4*)(cb + (2 * p + 1) * 4);
    g_pk.n0[p] = pack2(-2.f * c0.x, -2.f * c1.x);
    g_pk.n1[p] = pack2(-2.f * c0.y, -2.f * c1.y);
    g_pk.n2[p] = pack2(-2.f * c0.z, -2.f * c1.z);
    g_pk.n3[p] = pack2(-2.f * c0.w, -2.f * c1.w);
    float b0 = c0.x*c0.x + c0.y*c0.y + c0.z*c0.z + c0.w*c0.w
             + lpmf[2*p]     * NEG_INV_LN2 * INV_LMBDA;
    float b1 = c1.x*c1.x + c1.y*c1.y + c1.z*c1.z + c1.w*c1.w
             + lpmf[2*p + 1] * NEG_INV_LN2 * INV_LMBDA;
    g_pk.bias[p] = pack2(b0, b1);
}

__global__ __launch_bounds__(64)
void vq_main(const float* __restrict__ lat,
             const float* __restrict__ cb,
             const float* __restrict__ lpmf,
             float* __restrict__ out)
{
    // Only the NON-uniform accesses stay in SMEM (gather by per-thread index)
    __shared__ float4 s_cw[KCODE];
    __shared__ float  s_l2p[KCODE];
    __shared__ float  s_ind[256];     // this quarter's 256 chunk indices
    __shared__ float  s_rm[2];
    __shared__ float  s_rr[2];
    __shared__ int    s_last;

    const int tid = threadIdx.x;         // 0..63
    const int blk = blockIdx.x;          // 0..3071
    const int b   = blk >> 2;            // 0..767
    const int wq  = blk & 3;             // quarter: w in [wq*16, wq*16+16)

    // ---- gather-table prep (tiny; cb/lpmf stay hot in L2 across blocks) ----
    #pragma unroll
    for (int i = 0; i < 4; ++i) {
        const int k = tid * 4 + i;
        float4 ck = *(const float4*)(cb + k * 4);
        s_cw[k]  = ck;
        s_l2p[k] = lpmf[k] * NEG_INV_LN2;
    }
    __syncthreads();

    // ---- thread -> 4 chunks (c, w0..w0+3) ----
    const int wl = (tid & 3) * 4;        // local w group of 4 within this quarter
    const int w0 = wq * 16 + wl;         // global w
    const int c  = tid >> 2;             // 0..15 chunk row-group

    const int h0 = 4 * c, h1 = h0 + 1, h2 = h0 + 2, h3 = h0 + 3;
    const int s2 = (h2 < HH) ? h2 : h2 - 2;   // c==15: 62 -> 60
    const int s3 = (h3 < HH) ? h3 : h3 - 2;   // c==15: 63 -> 61

    const float* base = lat + (size_t)b * (HH * WW) + w0;
    float4 v0 = *(const float4*)(base + h0 * WW);
    float4 v1 = *(const float4*)(base + h1 * WW);
    float4 v2 = *(const float4*)(base + s2 * WW);
    float4 v3 = *(const float4*)(base + s3 * WW);

    const float* f0 = (const float*)&v0;
    const float* f1 = (const float*)&v1;
    const float* f2 = (const float*)&v2;
    const float* f3 = (const float*)&v3;

    // chunk j (w = w0+j) has elements (f0[j], f1[j], f2[j], f3[j]); pack duplicated
    u64 xq0[4], xq1[4], xq2[4], xq3[4];
    #pragma unroll
    for (int j = 0; j < 4; ++j) {
        xq0[j] = pack2(f0[j], f0[j]);
        xq1[j] = pack2(f1[j], f1[j]);
        xq2[j] = pack2(f2[j], f2[j]);
        xq3[j] = pack2(f3[j], f3[j]);
    }

    // ---- main loop: value-only min over 32 groups of 8 codewords ----
    // score_k = (||c_k||^2 + log2_pmf_k/lambda) - 2 * <x, c_k>
    // Codebook indices are warp-uniform -> constant/uniform-register path (no LDS).
    float best[4] = {3.4e38f, 3.4e38f, 3.4e38f, 3.4e38f};
    int   bgrp[4] = {0, 0, 0, 0};

    #pragma unroll 2
    for (int g = 0; g < 32; ++g) {
        float pm[4][4];
        #pragma unroll
        for (int q = 0; q < 4; ++q) {
            const int p = (g << 2) + q;
            const u64 n0 = c_pk.n0[p];
            const u64 n1 = c_pk.n1[p];
            const u64 n2 = c_pk.n2[p];
            const u64 n3 = c_pk.n3[p];
            const u64 bias = c_pk.bias[p];
            #pragma unroll
            for (int j = 0; j < 4; ++j) {
                u64 a = fma2(xq0[j], n0, bias);
                a = fma2(xq1[j], n1, a);
                a = fma2(xq2[j], n2, a);
                a = fma2(xq3[j], n3, a);
                float lo, hi; unpack2(a, lo, hi);
                pm[j][q] = fminf(lo, hi);
            }
        }
        #pragma unroll
        for (int j = 0; j < 4; ++j) {
            float gm = fminf(fminf(pm[j][0], pm[j][1]), fminf(pm[j][2], pm[j][3]));
            // strict < keeps the earliest group on ties (first-index-wins)
            if (gm < best[j]) { best[j] = gm; bgrp[j] = g; }
        }
    }

    // ---- index recovery: recompute the winning group's 8 scores bit-exactly,
    //      descending overwrite-on-equality -> lowest k wins (jnp.argmin ties) ----
    int bi[4];
    #pragma unroll
    for (int j = 0; j < 4; ++j) {
        int idx = 0;
        const int pbase = bgrp[j] << 2;
        #pragma unroll
        for (int q = 3; q >= 0; --q) {
            const int p = pbase + q;
            u64 a = fma2(xq0[j], c_pk.n0[p], c_pk.bias[p]);
            a = fma2(xq1[j], c_pk.n1[p], a);
            a = fma2(xq2[j], c_pk.n2[p], a);
            a = fma2(xq3[j], c_pk.n3[p], a);
            float lo, hi; unpack2(a, lo, hi);
            if (hi == best[j]) idx = 2 * p + 1;
            if (lo == best[j]) idx = 2 * p;
        }
        bi[j] = idx;
    }

    // ---- gather chosen codewords ----
    float4 q0 = s_cw[bi[0]];
    float4 q1 = s_cw[bi[1]];
    float4 q2 = s_cw[bi[2]];
    float4 q3 = s_cw[bi[3]];

    // ql writes: row d at (h_d, w0..w0+3) = (q0[d], q1[d], q2[d], q3[d]) -> STG.128
    float* oql = out + (size_t)b * (HH * WW) + w0;
    {
        float4 r0 = make_float4(q0.x, q1.x, q2.x, q3.x);
        float4 r1 = make_float4(q0.y, q1.y, q2.y, q3.y);
        *(float4*)(oql + h0 * WW) = r0;
        *(float4*)(oql + h1 * WW) = r1;
        if (h2 < HH) {
            float4 r2 = make_float4(q0.z, q1.z, q2.z, q3.z);
            *(float4*)(oql + h2 * WW) = r2;
        }
        if (h3 < HH) {
            float4 r3 = make_float4(q0.w, q1.w, q2.w, q3.w);
            *(float4*)(oql + h3 * WW) = r3;
        }
    }

    // mse / rate partials (all 16 elements count, incl. padded duplicates)
    float lm, lr;
    {
        float d00 = q0.x - f0[0], d01 = q0.y - f1[0], d02 = q0.z - f2[0], d03 = q0.w - f3[0];
        float d10 = q1.x - f0[1], d11 = q1.y - f1[1], d12 = q1.z - f2[1], d13 = q1.w - f3[1];
        float d20 = q2.x - f0[2], d21 = q2.y - f1[2], d22 = q2.z - f2[2], d23 = q2.w - f3[2];
        float d30 = q3.x - f0[3], d31 = q3.y - f1[3], d32 = q3.z - f2[3], d33 = q3.w - f3[3];
        lm = d00*d00 + d01*d01 + d02*d02 + d03*d03
           + d10*d10 + d11*d11 + d12*d12 + d13*d13
           + d20*d20 + d21*d21 + d22*d22 + d23*d23
           + d30*d30 + d31*d31 + d32*d32 + d33*d33;
        lr = s_l2p[bi[0]] + s_l2p[bi[1]] + s_l2p[bi[2]] + s_l2p[bi[3]];
    }

    // inds: flat m = b*1024 + w*16 + c; this quarter owns [b*1024 + wq*256, +256)
    s_ind[(wl + 0) * 16 + c] = (float)bi[0];
    s_ind[(wl + 1) * 16 + c] = (float)bi[1];
    s_ind[(wl + 2) * 16 + c] = (float)bi[2];
    s_ind[(wl + 3) * 16 + c] = (float)bi[3];

    // ---- deterministic block reduction (2 warps) ----
    #pragma unroll
    for (int o = 16; o > 0; o >>= 1) {
        lm += __shfl_down_sync(0xFFFFFFFFu, lm, o);
        lr += __shfl_down_sync(0xFFFFFFFFu, lr, o);
    }
    if ((tid & 31) == 0) { s_rm[tid >> 5] = lm; s_rr[tid >> 5] = lr; }
    __syncthreads();

    // coalesced inds writeout (256 floats by 64 threads)
    float* oind = out + OFF_INDS + (size_t)b * CHUNKS_PER_B + wq * 256;
    oind[tid]       = s_ind[tid];
    oind[tid + 64]  = s_ind[tid + 64];
    oind[tid + 128] = s_ind[tid + 128];
    oind[tid + 192] = s_ind[tid + 192];

    if (tid == 0) {
        g_pmse[blk]  = s_rm[0] + s_rm[1];
        g_prate[blk] = s_rr[0] + s_rr[1];
        __threadfence();
        int v = atomicAdd(&g_count, 1);
        s_last = (v == NB4 - 1);
    }
    __syncthreads();

    // ---- fused finalize: last block reduces the 3072 partials (fixed order) ----
    if (s_last) {
        __threadfence();   // acquire: make all blocks' partials visible
        float a = 0.f, r = 0.f;
        #pragma unroll
        for (int i = 0; i < 48; ++i) {      // 3072 = 64*48, fixed order
            a += g_pmse[tid + i * 64];
            r += g_prate[tid + i * 64];
        }
        s_ind[tid]      = a;                // reuse smem
        s_ind[tid + 64] = r;
        __syncthreads();
        #pragma unroll
        for (int s = 32; s > 0; s >>= 1) {
            if (tid < s) {
                s_ind[tid]      += s_ind[tid + s];
                s_ind[64 + tid] += s_ind[64 + tid + s];
            }
            __syncthreads();
        }
        if (tid == 0) {
            out[OFF_MSE]   = s_ind[0] * (1.0f / MSE_COUNT);
            out[OFF_RATE]  = s_ind[64];
            out[OFF_PRIOR] = 0.f;
            out[OFF_PARAM] = 0.f;
            g_count = 0;   // reset for next graph replay
        }
    }
}

extern "C" void kernel_launch(void* const* d_in, const int* in_sizes, int n_in,
                              void* d_out, int out_size)
{
    const float* lat  = (const float*)d_in[0];   // latents  (4,192,62,64)
    const float* cb   = (const float*)d_in[1];   // codebook (256,4)
    const float* lpmf = (const float*)d_in[2];   // log_pmf  (256,)
    float* out = (float*)d_out;

    // 1) pack codebook into staging buffer
    vq_prep<<<1, NPAIR>>>(cb, lpmf);
    // 2) stage -> __constant__ (device-to-device async copy; graph-capturable)
    void* src = nullptr;
    cudaGetSymbolAddress(&src, g_pk);
    cudaMemcpyToSymbolAsync(c_pk, src, sizeof(PK), 0, cudaMemcpyDeviceToDevice);
    // 3) main kernel reads codebook via the constant/uniform path
    vq_main<<<NB4, 64>>>(lat, cb, lpmf, out);
}

// round 14
// speedup vs baseline: 1.7224x; 1.7224x over previous
#include <cuda_runtime.h>

// Problem constants
#define NB      768          // N*C
#define NB4     3072         // quarter-tiles
#define HH      62
#define WW      64
#define KCODE   256
#define NBLK    64           // codebook blocks of 2 pairs (4 codewords)
#define CHUNKS_PER_B 1024    // W * Hp / D
#define M_TOTAL (NB * CHUNKS_PER_B)          // 786432
#define QL_ELEMS (NB * HH * WW)              // 3047424
#define OFF_MSE   QL_ELEMS
#define OFF_INDS  (QL_ELEMS + 1)
#define OFF_RATE  (OFF_INDS + M_TOTAL)
#define OFF_PRIOR (OFF_RATE + 1)
#define OFF_PARAM (OFF_RATE + 2)
#define MSE_COUNT 3145728.0f                 // NB * 1024 * 4

#define NEG_INV_LN2 (-1.4426950408889634f)
#define INV_LMBDA   100.0f

typedef unsigned long long u64;

// Deterministic per-tile partials + completion counter
__device__ float g_pmse[NB4];
__device__ float g_prate[NB4];
__device__ int   g_count;        // zero-init; last block resets it -> graph-replayable

__device__ __forceinline__ u64 pack2(float lo, float hi) {
    u64 r; asm("mov.b64 %0,{%1,%2};" : "=l"(r) : "f"(lo), "f"(hi)); return r;
}
__device__ __forceinline__ void unpack2(u64 v, float& lo, float& hi) {
    asm("mov.b64 {%0,%1},%2;" : "=f"(lo), "=f"(hi) : "l"(v));
}
// packed dual-fp32 FMA (Blackwell f32x2 pipe; 2 MACs per issue slot)
__device__ __forceinline__ u64 fma2(u64 a, u64 b, u64 c) {
    u64 d; asm("fma.rn.f32x2 %0,%1,%2,%3;" : "=l"(d) : "l"(a), "l"(b), "l"(c)); return d;
}

__global__ __launch_bounds__(64)
void vq_main(const float* __restrict__ lat,
             const float* __restrict__ cb,
             const float* __restrict__ lpmf,
             float* __restrict__ out)
{
    // Blocked packed codebook: block r covers pairs {2r, 2r+1} = codewords 4r..4r+3.
    // Record = 5 x ulonglong2 = 5 x LDS.128:
    //   [0] {n0,n1} of pair A   [1] {n2,n3} of pair A
    //   [2] {n0,n1} of pair B   [3] {n2,n3} of pair B
    //   [4] {biasA, biasB}
    __shared__ ulonglong2 s_cb[NBLK * 5];
    __shared__ float4     s_cw[KCODE];
    __shared__ float      s_l2p[KCODE];
    __shared__ float      s_ind[256];     // this quarter's 256 chunk indices
    __shared__ float      s_rm[2];
    __shared__ float      s_rr[2];
    __shared__ int        s_last;

    const int tid = threadIdx.x;         // 0..63
    const int blk = blockIdx.x;          // 0..3071
    const int b   = blk >> 2;            // 0..767
    const int wq  = blk & 3;             // quarter: w in [wq*16, wq*16+16)

    // ---- codebook prep (tiny; cb/lpmf stay hot in L2 across blocks) ----
    #pragma unroll
    for (int i = 0; i < 4; ++i) {
        const int k = tid * 4 + i;
        float4 ck = *(const float4*)(cb + k * 4);
        s_cw[k]  = ck;
        s_l2p[k] = lpmf[k] * NEG_INV_LN2;
    }
    {
        // thread t builds block t: pairs 2t (codewords 4t,4t+1), 2t+1 (4t+2,4t+3)
        const int r  = tid;
        float4 c0 = *(const float4*)(cb + (4 * r + 0) * 4);
        float4 c1 = *(const float4*)(cb + (4 * r + 1) * 4);
        float4 c2 = *(const float4*)(cb + (4 * r + 2) * 4);
        float4 c3 = *(const float4*)(cb + (4 * r + 3) * 4);
        ulonglong2 a01, a23, b01, b23, bias;
        a01.x = pack2(-2.f * c0.x, -2.f * c1.x);
        a01.y = pack2(-2.f * c0.y, -2.f * c1.y);
        a23.x = pack2(-2.f * c0.z, -2.f * c1.z);
        a23.y = pack2(-2.f * c0.w, -2.f * c1.w);
        b01.x = pack2(-2.f * c2.x, -2.f * c3.x);
        b01.y = pack2(-2.f * c2.y, -2.f * c3.y);
        b23.x = pack2(-2.f * c2.z, -2.f * c3.z);
        b23.y = pack2(-2.f * c2.w, -2.f * c3.w);
        float e0 = c0.x*c0.x + c0.y*c0.y + c0.z*c0.z + c0.w*c0.w
                 + lpmf[4*r + 0] * NEG_INV_LN2 * INV_LMBDA;
        float e1 = c1.x*c1.x + c1.y*c1.y + c1.z*c1.z + c1.w*c1.w
                 + lpmf[4*r + 1] * NEG_INV_LN2 * INV_LMBDA;
        float e2 = c2.x*c2.x + c2.y*c2.y + c2.z*c2.z + c2.w*c2.w
                 + lpmf[4*r + 2] * NEG_INV_LN2 * INV_LMBDA;
        float e3 = c3.x*c3.x + c3.y*c3.y + c3.z*c3.z + c3.w*c3.w
                 + lpmf[4*r + 3] * NEG_INV_LN2 * INV_LMBDA;
        bias.x = pack2(e0, e1);
        bias.y = pack2(e2, e3);
        s_cb[r * 5 + 0] = a01;
        s_cb[r * 5 + 1] = a23;
        s_cb[r * 5 + 2] = b01;
        s_cb[r * 5 + 3] = b23;
        s_cb[r * 5 + 4] = bias;
    }
    __syncthreads();

    // ---- thread -> 4 chunks (c, w0..w0+3) ----
    const int wl = (tid & 3) * 4;        // local w group of 4 within this quarter
    const int w0 = wq * 16 + wl;         // global w
    const int c  = tid >> 2;             // 0..15 chunk row-group

    const int h0 = 4 * c, h1 = h0 + 1, h2 = h0 + 2, h3 = h0 + 3;
    const int s2 = (h2 < HH) ? h2 : h2 - 2;   // c==15: 62 -> 60
    const int s3 = (h3 < HH) ? h3 : h3 - 2;   // c==15: 63 -> 61

    const float* base = lat + (size_t)b * (HH * WW) + w0;
    float4 v0 = *(const float4*)(base + h0 * WW);
    float4 v1 = *(const float4*)(base + h1 * WW);
    float4 v2 = *(const float4*)(base + s2 * WW);
    float4 v3 = *(const float4*)(base + s3 * WW);

    const float* f0 = (const float*)&v0;
    const float* f1 = (const float*)&v1;
    const float* f2 = (const float*)&v2;
    const float* f3 = (const float*)&v3;

    // chunk j (w = w0+j) has elements (f0[j], f1[j], f2[j], f3[j]); pack duplicated
    u64 xq0[4], xq1[4], xq2[4], xq3[4];
    #pragma unroll
    for (int j = 0; j < 4; ++j) {
        xq0[j] = pack2(f0[j], f0[j]);
        xq1[j] = pack2(f1[j], f1[j]);
        xq2[j] = pack2(f2[j], f2[j]);
        xq3[j] = pack2(f3[j], f3[j]);
    }

    // ---- main loop: value-only min over 16 groups of 16 codewords ----
    // score_k = (||c_k||^2 + log2_pmf_k/lambda) - 2 * <x, c_k>
    float best[4] = {3.4e38f, 3.4e38f, 3.4e38f, 3.4e38f};
    int   bgrp[4] = {0, 0, 0, 0};

    #pragma unroll 1
    for (int g = 0; g < 16; ++g) {
        float gm[4];
        #pragma unroll
        for (int rb = 0; rb < 4; ++rb) {
            const ulonglong2* rec = s_cb + (g * 4 + rb) * 5;
            ulonglong2 a01  = rec[0];
            ulonglong2 a23  = rec[1];
            ulonglong2 b01  = rec[2];
            ulonglong2 b23  = rec[3];
            ulonglong2 bias = rec[4];
            #pragma unroll
            for (int j = 0; j < 4; ++j) {
                u64 sa = fma2(xq0[j], a01.x, bias.x);
                sa = fma2(xq1[j], a01.y, sa);
                sa = fma2(xq2[j], a23.x, sa);
                sa = fma2(xq3[j], a23.y, sa);
                u64 sb = fma2(xq0[j], b01.x, bias.y);
                sb = fma2(xq1[j], b01.y, sb);
                sb = fma2(xq2[j], b23.x, sb);
                sb = fma2(xq3[j], b23.y, sb);
                float la, ha, lb, hb;
                unpack2(sa, la, ha);
                unpack2(sb, lb, hb);
                float m = fminf(fminf(la, ha), fminf(lb, hb));
                gm[j] = (rb == 0) ? m : fminf(gm[j], m);
            }
        }
        #pragma unroll
        for (int j = 0; j < 4; ++j) {
            // strict < keeps the earliest group on ties (first-index-wins)
            if (gm[j] < best[j]) { best[j] = gm[j]; bgrp[j] = g; }
        }
    }

    // ---- index recovery: recompute the winning group's 16 scores bit-exactly,
    //      descending overwrite-on-equality -> lowest k wins (jnp.argmin ties) ----
    int bi[4];
    #pragma unroll
    for (int j = 0; j < 4; ++j) {
        int idx = 0;
        const int rbase = bgrp[j] * 4;      // first block of the group
        #pragma unroll
        for (int rb = 3; rb >= 0; --rb) {
            const ulonglong2* rec = s_cb + (rbase + rb) * 5;
            ulonglong2 a01  = rec[0];
            ulonglong2 a23  = rec[1];
            ulonglong2 b01  = rec[2];
            ulonglong2 b23  = rec[3];
            ulonglong2 bias = rec[4];
            u64 sa = fma2(xq0[j], a01.x, bias.x);
            sa = fma2(xq1[j], a01.y, sa);
            sa = fma2(xq2[j], a23.x, sa);
            sa = fma2(xq3[j], a23.y, sa);
            u64 sb = fma2(xq0[j], b01.x, bias.y);
            sb = fma2(xq1[j], b01.y, sb);
            sb = fma2(xq2[j], b23.x, sb);
            sb = fma2(xq3[j], b23.y, sb);
            float la, ha, lb, hb;
            unpack2(sa, la, ha);
            unpack2(sb, lb, hb);
            const int k0 = (bgrp[j] * 4 + rb) * 4;   // first codeword of this block
            // descending codeword order: k0+3, k0+2, k0+1, k0
            if (hb == best[j]) idx = k0 + 3;
            if (lb == best[j]) idx = k0 + 2;
            if (ha == best[j]) idx = k0 + 1;
            if (la == best[j]) idx = k0;
        }
        bi[j] = idx;
    }

    // ---- gather chosen codewords ----
    float4 q0 = s_cw[bi[0]];
    float4 q1 = s_cw[bi[1]];
    float4 q2 = s_cw[bi[2]];
    float4 q3 = s_cw[bi[3]];

    // ql writes: row d at (h_d, w0..w0+3) = (q0[d], q1[d], q2[d], q3[d]) -> STG.128
    float* oql = out + (size_t)b * (HH * WW) + w0;
    {
        float4 r0 = make_float4(q0.x, q1.x, q2.x, q3.x);
        float4 r1 = make_float4(q0.y, q1.y, q2.y, q3.y);
        *(float4*)(oql + h0 * WW) = r0;
        *(float4*)(oql + h1 * WW) = r1;
        if (h2 < HH) {
            float4 r2 = make_float4(q0.z, q1.z, q2.z, q3.z);
            *(float4*)(oql + h2 * WW) = r2;
        }
        if (h3 < HH) {
            float4 r3 = make_float4(q0.w, q1.w, q2.w, q3.w);
            *(float4*)(oql + h3 * WW) = r3;
        }
    }

    // mse / rate partials (all 16 elements count, incl. padded duplicates)
    float lm, lr;
    {
        float d00 = q0.x - f0[0], d01 = q0.y - f1[0], d02 = q0.z - f2[0], d03 = q0.w - f3[0];
        float d10 = q1.x - f0[1], d11 = q1.y - f1[1], d12 = q1.z - f2[1], d13 = q1.w - f3[1];
        float d20 = q2.x - f0[2], d21 = q2.y - f1[2], d22 = q2.z - f2[2], d23 = q2.w - f3[2];
        float d30 = q3.x - f0[3], d31 = q3.y - f1[3], d32 = q3.z - f2[3], d33 = q3.w - f3[3];
        lm = d00*d00 + d01*d01 + d02*d02 + d03*d03
           + d10*d10 + d11*d11 + d12*d12 + d13*d13
           + d20*d20 + d21*d21 + d22*d22 + d23*d23
           + d30*d30 + d31*d31 + d32*d32 + d33*d33;
        lr = s_l2p[bi[0]] + s_l2p[bi[1]] + s_l2p[bi[2]] + s_l2p[bi[3]];
    }

    // inds: flat m = b*1024 + w*16 + c; this quarter owns [b*1024 + wq*256, +256)
    s_ind[(wl + 0) * 16 + c] = (float)bi[0];
    s_ind[(wl + 1) * 16 + c] = (float)bi[1];
    s_ind[(wl + 2) * 16 + c] = (float)bi[2];
    s_ind[(wl + 3) * 16 + c] = (float)bi[3];

    // ---- deterministic block reduction (2 warps) ----
    #pragma unroll
    for (int o = 16; o > 0; o >>= 1) {
        lm += __shfl_down_sync(0xFFFFFFFFu, lm, o);
        lr += __shfl_down_sync(0xFFFFFFFFu, lr, o);
    }
    if ((tid & 31) == 0) { s_rm[tid >> 5] = lm; s_rr[tid >> 5] = lr; }
    __syncthreads();

    // coalesced inds writeout (256 floats by 64 threads)
    float* oind = out + OFF_INDS + (size_t)b * CHUNKS_PER_B + wq * 256;
    oind[tid]       = s_ind[tid];
    oind[tid + 64]  = s_ind[tid + 64];
    oind[tid + 128] = s_ind[tid + 128];
    oind[tid + 192] = s_ind[tid + 192];

    if (tid == 0) {
        g_pmse[blk]  = s_rm[0] + s_rm[1];
        g_prate[blk] = s_rr[0] + s_rr[1];
        __threadfence();
        int v = atomicAdd(&g_count, 1);
        s_last = (v == NB4 - 1);
    }
    __syncthreads();

    // ---- fused finalize: last block reduces the 3072 partials (fixed order) ----
    if (s_last) {
        __threadfence();   // acquire: make all blocks' partials visible
        float a = 0.f, r = 0.f;
        #pragma unroll
        for (int i = 0; i < 48; ++i) {      // 3072 = 64*48, fixed order
            a += g_pmse[tid + i * 64];
            r += g_prate[tid + i * 64];
        }
        s_ind[tid]      = a;                // reuse smem
        s_ind[tid + 64] = r;
        __syncthreads();
        #pragma unroll
        for (int s = 32; s > 0; s >>= 1) {
            if (tid < s) {
                s_ind[tid]      += s_ind[tid + s];
                s_ind[64 + tid] += s_ind[64 + tid + s];
            }
            __syncthreads();
        }
        if (tid == 0) {
            out[OFF_MSE]   = s_ind[0] * (1.0f / MSE_COUNT);
            out[OFF_RATE]  = s_ind[64];
            out[OFF_PRIOR] = 0.f;
            out[OFF_PARAM] = 0.f;
            g_count = 0;   // reset for next graph replay
        }
    }
}

extern "C" void kernel_launch(void* const* d_in, const int* in_sizes, int n_in,
                              void* d_out, int out_size)
{
    const float* lat  = (const float*)d_in[0];   // latents  (4,192,62,64)
    const float* cb   = (const float*)d_in[1];   // codebook (256,4)
    const float* lpmf = (const float*)d_in[2];   // log_pmf  (256,)
    float* out = (float*)d_out;

    vq_main<<<NB4, 64>>>(lat, cb, lpmf, out);
}

// round 15
// speedup vs baseline: 2.6410x; 1.5333x over previous
#include <cuda_runtime.h>

// Problem constants
#define NB      768          // N*C
#define NB4     3072         // quarter-tiles total
#define GRID    1536         // CTAs; each processes 2 tiles -> exactly 1 resident wave
#define HH      62
#define WW      64
#define KCODE   256
#define NPAIR   128
#define CHUNKS_PER_B 1024    // W * Hp / D
#define M_TOTAL (NB * CHUNKS_PER_B)          // 786432
#define QL_ELEMS (NB * HH * WW)              // 3047424
#define OFF_MSE   QL_ELEMS
#define OFF_INDS  (QL_ELEMS + 1)
#define OFF_RATE  (OFF_INDS + M_TOTAL)
#define OFF_PRIOR (OFF_RATE + 1)
#define OFF_PARAM (OFF_RATE + 2)
#define MSE_COUNT 3145728.0f                 // NB * 1024 * 4

#define NEG_INV_LN2 (-1.4426950408889634f)
#define INV_LMBDA   100.0f

typedef unsigned long long u64;

// Deterministic per-tile partials + completion counter
__device__ float g_pmse[NB4];
__device__ float g_prate[NB4];
__device__ int   g_count;        // zero-init; last tile resets it -> graph-replayable

__device__ __forceinline__ u64 pack2(float lo, float hi) {
    u64 r; asm("mov.b64 %0,{%1,%2};" : "=l"(r) : "f"(lo), "f"(hi)); return r;
}
__device__ __forceinline__ void unpack2(u64 v, float& lo, float& hi) {
    asm("mov.b64 {%0,%1},%2;" : "=f"(lo), "=f"(hi) : "l"(v));
}
// packed dual-fp32 FMA (Blackwell f32x2 pipe; 2 MACs per issue slot)
__device__ __forceinline__ u64 fma2(u64 a, u64 b, u64 c) {
    u64 d; asm("fma.rn.f32x2 %0,%1,%2,%3;" : "=l"(d) : "l"(a), "l"(b), "l"(c)); return d;
}

__global__ __launch_bounds__(64)
void vq_main(const float* __restrict__ lat,
             const float* __restrict__ cb,
             const float* __restrict__ lpmf,
             float* __restrict__ out)
{
    // Packed codebook: pair p -> {-2*c[2p][d], -2*c[2p+1][d]} split for LDS.128 loads
    __shared__ ulonglong2 s_n01[NPAIR];   // {n_d0, n_d1}
    __shared__ ulonglong2 s_n23[NPAIR];   // {n_d2, n_d3}
    __shared__ u64        s_bias[NPAIR];
    __shared__ float4     s_cw[KCODE];
    __shared__ float      s_l2p[KCODE];
    __shared__ float      s_ind[256];     // current quarter's 256 chunk indices
    __shared__ float      s_rm[2];
    __shared__ float      s_rr[2];
    __shared__ int        s_last;

    const int tid = threadIdx.x;         // 0..63

    // ---- codebook prep ONCE per CTA (amortized over 2 tiles) ----
    #pragma unroll
    for (int i = 0; i < 4; ++i) {
        const int k = tid * 4 + i;
        float4 ck = *(const float4*)(cb + k * 4);
        s_cw[k]  = ck;
        s_l2p[k] = lpmf[k] * NEG_INV_LN2;
    }
    #pragma unroll
    for (int i = 0; i < 2; ++i) {
        const int p = tid * 2 + i;
        float4 c0 = *(const float4*)(cb + (2 * p) * 4);
        float4 c1 = *(const float4*)(cb + (2 * p + 1) * 4);
        ulonglong2 a, bq;
        a.x  = pack2(-2.f * c0.x, -2.f * c1.x);
        a.y  = pack2(-2.f * c0.y, -2.f * c1.y);
        bq.x = pack2(-2.f * c0.z, -2.f * c1.z);
        bq.y = pack2(-2.f * c0.w, -2.f * c1.w);
        s_n01[p] = a;
        s_n23[p] = bq;
        float b0 = c0.x*c0.x + c0.y*c0.y + c0.z*c0.z + c0.w*c0.w
                 + lpmf[2*p]     * NEG_INV_LN2 * INV_LMBDA;
        float b1 = c1.x*c1.x + c1.y*c1.y + c1.z*c1.z + c1.w*c1.w
                 + lpmf[2*p + 1] * NEG_INV_LN2 * INV_LMBDA;
        s_bias[p] = pack2(b0, b1);
    }
    __syncthreads();

    // ---- two tiles per CTA: blk = blockIdx.x and blockIdx.x + GRID ----
    #pragma unroll 1
    for (int t = 0; t < 2; ++t) {
        const int blk = blockIdx.x + t * GRID;   // 0..3071
        const int b   = blk >> 2;                // 0..767
        const int wq  = blk & 3;                 // quarter: w in [wq*16, wq*16+16)

        if (t == 1) __syncthreads();             // protect s_ind/s_rm reuse

        // ---- thread -> 4 chunks (c, w0..w0+3) ----
        const int wl = (tid & 3) * 4;        // local w group of 4 within this quarter
        const int w0 = wq * 16 + wl;         // global w
        const int c  = tid >> 2;             // 0..15 chunk row-group

        const int h0 = 4 * c, h1 = h0 + 1, h2 = h0 + 2, h3 = h0 + 3;
        const int s2 = (h2 < HH) ? h2 : h2 - 2;   // c==15: 62 -> 60
        const int s3 = (h3 < HH) ? h3 : h3 - 2;   // c==15: 63 -> 61

        const float* base = lat + (size_t)b * (HH * WW) + w0;
        float4 v0 = *(const float4*)(base + h0 * WW);
        float4 v1 = *(const float4*)(base + h1 * WW);
        float4 v2 = *(const float4*)(base + s2 * WW);
        float4 v3 = *(const float4*)(base + s3 * WW);

        const float* f0 = (const float*)&v0;
        const float* f1 = (const float*)&v1;
        const float* f2 = (const float*)&v2;
        const float* f3 = (const float*)&v3;

        // chunk j (w = w0+j) has elements (f0[j], f1[j], f2[j], f3[j]); pack duplicated
        u64 xq0[4], xq1[4], xq2[4], xq3[4];
        #pragma unroll
        for (int j = 0; j < 4; ++j) {
            xq0[j] = pack2(f0[j], f0[j]);
            xq1[j] = pack2(f1[j], f1[j]);
            xq2[j] = pack2(f2[j], f2[j]);
            xq3[j] = pack2(f3[j], f3[j]);
        }

        // ---- main loop: value-only min over 32 groups of 8 codewords ----
        // score_k = (||c_k||^2 + log2_pmf_k/lambda) - 2 * <x, c_k>
        float best[4] = {3.4e38f, 3.4e38f, 3.4e38f, 3.4e38f};
        int   bgrp[4] = {0, 0, 0, 0};

        #pragma unroll 2
        for (int g = 0; g < 32; ++g) {
            float pm[4][4];
            #pragma unroll
            for (int q = 0; q < 4; ++q) {
                const int p = (g << 2) + q;
                ulonglong2 n01 = s_n01[p];
                ulonglong2 n23 = s_n23[p];
                u64 bias = s_bias[p];
                #pragma unroll
                for (int j = 0; j < 4; ++j) {
                    u64 a = fma2(xq0[j], n01.x, bias);
                    a = fma2(xq1[j], n01.y, a);
                    a = fma2(xq2[j], n23.x, a);
                    a = fma2(xq3[j], n23.y, a);
                    float lo, hi; unpack2(a, lo, hi);
                    pm[j][q] = fminf(lo, hi);
                }
            }
            #pragma unroll
            for (int j = 0; j < 4; ++j) {
                float gm = fminf(fminf(pm[j][0], pm[j][1]), fminf(pm[j][2], pm[j][3]));
                // strict < keeps the earliest group on ties (first-index-wins)
                if (gm < best[j]) { best[j] = gm; bgrp[j] = g; }
            }
        }

        // ---- index recovery: recompute winning group's 8 scores bit-exactly,
        //      descending overwrite-on-equality -> lowest k wins (jnp.argmin ties) ----
        int bi[4];
        #pragma unroll
        for (int j = 0; j < 4; ++j) {
            int idx = 0;
            const int pbase = bgrp[j] << 2;
            #pragma unroll
            for (int q = 3; q >= 0; --q) {
                const int p = pbase + q;
                ulonglong2 n01 = s_n01[p];
                ulonglong2 n23 = s_n23[p];
                u64 bias = s_bias[p];
                u64 a = fma2(xq0[j], n01.x, bias);
                a = fma2(xq1[j], n01.y, a);
                a = fma2(xq2[j], n23.x, a);
                a = fma2(xq3[j], n23.y, a);
                float lo, hi; unpack2(a, lo, hi);
                if (hi == best[j]) idx = 2 * p + 1;
                if (lo == best[j]) idx = 2 * p;
            }
            bi[j] = idx;
        }

        // ---- gather chosen codewords ----
        float4 q0 = s_cw[bi[0]];
        float4 q1 = s_cw[bi[1]];
        float4 q2 = s_cw[bi[2]];
        float4 q3 = s_cw[bi[3]];

        // ql writes: row d at (h_d, w0..w0+3) = (q0[d], q1[d], q2[d], q3[d]) -> STG.128
        float* oql = out + (size_t)b * (HH * WW) + w0;
        {
            float4 r0 = make_float4(q0.x, q1.x, q2.x, q3.x);
            float4 r1 = make_float4(q0.y, q1.y, q2.y, q3.y);
            *(float4*)(oql + h0 * WW) = r0;
            *(float4*)(oql + h1 * WW) = r1;
            if (h2 < HH) {
                float4 r2 = make_float4(q0.z, q1.z, q2.z, q3.z);
                *(float4*)(oql + h2 * WW) = r2;
            }
            if (h3 < HH) {
                float4 r3 = make_float4(q0.w, q1.w, q2.w, q3.w);
                *(float4*)(oql + h3 * WW) = r3;
            }
        }

        // mse / rate partials (all 16 elements count, incl. padded duplicates)
        float lm, lr;
        {
            float d00 = q0.x - f0[0], d01 = q0.y - f1[0], d02 = q0.z - f2[0], d03 = q0.w - f3[0];
            float d10 = q1.x - f0[1], d11 = q1.y - f1[1], d12 = q1.z - f2[1], d13 = q1.w - f3[1];
            float d20 = q2.x - f0[2], d21 = q2.y - f1[2], d22 = q2.z - f2[2], d23 = q2.w - f3[2];
            float d30 = q3.x - f0[3], d31 = q3.y - f1[3], d32 = q3.z - f2[3], d33 = q3.w - f3[3];
            lm = d00*d00 + d01*d01 + d02*d02 + d03*d03
               + d10*d10 + d11*d11 + d12*d12 + d13*d13
               + d20*d20 + d21*d21 + d22*d22 + d23*d23
               + d30*d30 + d31*d31 + d32*d32 + d33*d33;
            lr = s_l2p[bi[0]] + s_l2p[bi[1]] + s_l2p[bi[2]] + s_l2p[bi[3]];
        }

        // inds: flat m = b*1024 + w*16 + c; this quarter owns [b*1024 + wq*256, +256)
        s_ind[(wl + 0) * 16 + c] = (float)bi[0];
        s_ind[(wl + 1) * 16 + c] = (float)bi[1];
        s_ind[(wl + 2) * 16 + c] = (float)bi[2];
        s_ind[(wl + 3) * 16 + c] = (float)bi[3];

        // ---- deterministic block reduction (2 warps) ----
        #pragma unroll
        for (int o = 16; o > 0; o >>= 1) {
            lm += __shfl_down_sync(0xFFFFFFFFu, lm, o);
            lr += __shfl_down_sync(0xFFFFFFFFu, lr, o);
        }
        if ((tid & 31) == 0) { s_rm[tid >> 5] = lm; s_rr[tid >> 5] = lr; }
        __syncthreads();

        // coalesced inds writeout (256 floats by 64 threads)
        float* oind = out + OFF_INDS + (size_t)b * CHUNKS_PER_B + wq * 256;
        oind[tid]       = s_ind[tid];
        oind[tid + 64]  = s_ind[tid + 64];
        oind[tid + 128] = s_ind[tid + 128];
        oind[tid + 192] = s_ind[tid + 192];

        if (tid == 0) {
            g_pmse[blk]  = s_rm[0] + s_rm[1];
            g_prate[blk] = s_rr[0] + s_rr[1];
            __threadfence();
            int v = atomicAdd(&g_count, 1);
            s_last = (v == NB4 - 1);
        }
        __syncthreads();

        // ---- fused finalize: the tile that completes last reduces all partials ----
        if (s_last) {
            __threadfence();   // acquire: make all tiles' partials visible
            float a = 0.f, r = 0.f;
            #pragma unroll
            for (int i = 0; i < 48; ++i) {      // 3072 = 64*48, fixed order
                a += g_pmse[tid + i * 64];
                r += g_prate[tid + i * 64];
            }
            s_ind[tid]      = a;                // reuse smem
            s_ind[tid + 64] = r;
            __syncthreads();
            #pragma unroll
            for (int s = 32; s > 0; s >>= 1) {
                if (tid < s) {
                    s_ind[tid]      += s_ind[tid + s];
                    s_ind[64 + tid] += s_ind[64 + tid + s];
                }
                __syncthreads();
            }
            if (tid == 0) {
                out[OFF_MSE]   = s_ind[0] * (1.0f / MSE_COUNT);
                out[OFF_RATE]  = s_ind[64];
                out[OFF_PRIOR] = 0.f;
                out[OFF_PARAM] = 0.f;
                g_count = 0;   // reset for next graph replay
            }
        }
    }
}

extern "C" void kernel_launch(void* const* d_in, const int* in_sizes, int n_in,
                              void* d_out, int out_size)
{
    const float* lat  = (const float*)d_in[0];   // latents  (4,192,62,64)
    const float* cb   = (const float*)d_in[1];   // codebook (256,4)
    const float* lpmf = (const float*)d_in[2];   // log_pmf  (256,)
    float* out = (float*)d_out;

    vq_main<<<GRID, 64>>>(lat, cb, lpmf, out);
}

// round 16
// speedup vs baseline: 2.7782x; 1.0519x over previous
#include <cuda_runtime.h>

// Problem constants
#define NB      768          // N*C
#define NB4     3072         // quarter-tiles
#define HH      62
#define WW      64
#define KCODE   256
#define NPAIR   128
#define CHUNKS_PER_B 1024    // W * Hp / D
#define M_TOTAL (NB * CHUNKS_PER_B)          // 786432
#define QL_ELEMS (NB * HH * WW)              // 3047424
#define OFF_MSE   QL_ELEMS
#define OFF_INDS  (QL_ELEMS + 1)
#define OFF_RATE  (OFF_INDS + M_TOTAL)
#define OFF_PRIOR (OFF_RATE + 1)
#define OFF_PARAM (OFF_RATE + 2)
#define MSE_COUNT 3145728.0f                 // NB * 1024 * 4

#define NEG_INV_LN2 (-1.4426950408889634f)
#define INV_LMBDA   100.0f

typedef unsigned long long u64;

// Deterministic per-(quarter)block partials + completion counter
__device__ float g_pmse[NB4];
__device__ float g_prate[NB4];
__device__ int   g_count;        // zero-init; last block resets it -> graph-replayable

__device__ __forceinline__ u64 pack2(float lo, float hi) {
    u64 r; asm("mov.b64 %0,{%1,%2};" : "=l"(r) : "f"(lo), "f"(hi)); return r;
}
__device__ __forceinline__ void unpack2(u64 v, float& lo, float& hi) {
    asm("mov.b64 {%0,%1},%2;" : "=f"(lo), "=f"(hi) : "l"(v));
}
// packed dual-fp32 FMA (Blackwell f32x2 pipe; 2 MACs per issue slot)
__device__ __forceinline__ u64 fma2(u64 a, u64 b, u64 c) {
    u64 d; asm("fma.rn.f32x2 %0,%1,%2,%3;" : "=l"(d) : "l"(a), "l"(b), "l"(c)); return d;
}

__global__ __launch_bounds__(64)
void vq_main(const float* __restrict__ lat,
             const float* __restrict__ cb,
             const float* __restrict__ lpmf,
             float* __restrict__ out)
{
    // Packed codebook: pair p -> {-2*c[2p][d], -2*c[2p+1][d]} split for LDS.128 loads
    __shared__ ulonglong2 s_n01[NPAIR];   // {n_d0, n_d1}
    __shared__ ulonglong2 s_n23[NPAIR];   // {n_d2, n_d3}
    __shared__ u64        s_bias[NPAIR];
    __shared__ float4     s_cw[KCODE];
    __shared__ float      s_l2p[KCODE];
    __shared__ float      s_ind[256];     // this quarter's 256 chunk indices
    __shared__ float      s_rm[2];
    __shared__ float      s_rr[2];
    __shared__ int        s_last;

    const int tid = threadIdx.x;         // 0..63
    const int blk = blockIdx.x;          // 0..3071
    const int b   = blk >> 2;            // 0..767
    const int wq  = blk & 3;             // quarter: w in [wq*16, wq*16+16)

    // ---- codebook prep (tiny; stays hot in L2 across blocks) ----
    #pragma unroll
    for (int i = 0; i < 4; ++i) {
        const int k = tid * 4 + i;
        float4 ck = *(const float4*)(cb + k * 4);
        s_cw[k]  = ck;
        s_l2p[k] = lpmf[k] * NEG_INV_LN2;
    }
    #pragma unroll
    for (int i = 0; i < 2; ++i) {
        const int p = tid * 2 + i;
        float4 c0 = *(const float4*)(cb + (2 * p) * 4);
        float4 c1 = *(const float4*)(cb + (2 * p + 1) * 4);
        ulonglong2 a, bq;
        a.x  = pack2(-2.f * c0.x, -2.f * c1.x);
        a.y  = pack2(-2.f * c0.y, -2.f * c1.y);
        bq.x = pack2(-2.f * c0.z, -2.f * c1.z);
        bq.y = pack2(-2.f * c0.w, -2.f * c1.w);
        s_n01[p] = a;
        s_n23[p] = bq;
        float b0 = c0.x*c0.x + c0.y*c0.y + c0.z*c0.z + c0.w*c0.w
                 + lpmf[2*p]     * NEG_INV_LN2 * INV_LMBDA;
        float b1 = c1.x*c1.x + c1.y*c1.y + c1.z*c1.z + c1.w*c1.w
                 + lpmf[2*p + 1] * NEG_INV_LN2 * INV_LMBDA;
        s_bias[p] = pack2(b0, b1);
    }
    __syncthreads();

    // ---- thread -> 4 chunks (c, w0..w0+3) ----
    const int wl = (tid & 3) * 4;        // local w group of 4 within this quarter
    const int w0 = wq * 16 + wl;         // global w
    const int c  = tid >> 2;             // 0..15 chunk row-group

    const int h0 = 4 * c, h1 = h0 + 1, h2 = h0 + 2, h3 = h0 + 3;
    const int s2 = (h2 < HH) ? h2 : h2 - 2;   // c==15: 62 -> 60
    const int s3 = (h3 < HH) ? h3 : h3 - 2;   // c==15: 63 -> 61

    const float* base = lat + (size_t)b * (HH * WW) + w0;
    float4 v0 = *(const float4*)(base + h0 * WW);
    float4 v1 = *(const float4*)(base + h1 * WW);
    float4 v2 = *(const float4*)(base + s2 * WW);
    float4 v3 = *(const float4*)(base + s3 * WW);

    const float* f0 = (const float*)&v0;
    const float* f1 = (const float*)&v1;
    const float* f2 = (const float*)&v2;
    const float* f3 = (const float*)&v3;

    // chunk j (w = w0+j) has elements (f0[j], f1[j], f2[j], f3[j]); pack duplicated
    u64 xq0[4], xq1[4], xq2[4], xq3[4];
    #pragma unroll
    for (int j = 0; j < 4; ++j) {
        xq0[j] = pack2(f0[j], f0[j]);
        xq1[j] = pack2(f1[j], f1[j]);
        xq2[j] = pack2(f2[j], f2[j]);
        xq3[j] = pack2(f3[j], f3[j]);
    }

    // ---- main loop: value-only min over 32 groups of 8 codewords ----
    // score_k = (||c_k||^2 + log2_pmf_k/lambda) - 2 * <x, c_k>
    float best[4] = {3.4e38f, 3.4e38f, 3.4e38f, 3.4e38f};
    int   bgrp[4] = {0, 0, 0, 0};

    #pragma unroll 2
    for (int g = 0; g < 32; ++g) {
        float pm[4][4];
        #pragma unroll
        for (int q = 0; q < 4; ++q) {
            const int p = (g << 2) + q;
            ulonglong2 n01 = s_n01[p];
            ulonglong2 n23 = s_n23[p];
            u64 bias = s_bias[p];
            #pragma unroll
            for (int j = 0; j < 4; ++j) {
                u64 a = fma2(xq0[j], n01.x, bias);
                a = fma2(xq1[j], n01.y, a);
                a = fma2(xq2[j], n23.x, a);
                a = fma2(xq3[j], n23.y, a);
                float lo, hi; unpack2(a, lo, hi);
                pm[j][q] = fminf(lo, hi);
            }
        }
        #pragma unroll
        for (int j = 0; j < 4; ++j) {
            float gm = fminf(fminf(pm[j][0], pm[j][1]), fminf(pm[j][2], pm[j][3]));
            // strict < keeps the earliest group on ties (first-index-wins)
            if (gm < best[j]) { best[j] = gm; bgrp[j] = g; }
        }
    }

    // ---- index recovery: recompute the winning group's 8 scores bit-exactly,
    //      descending overwrite-on-equality -> lowest k wins (jnp.argmin ties) ----
    int bi[4];
    #pragma unroll
    for (int j = 0; j < 4; ++j) {
        int idx = 0;
        const int pbase = bgrp[j] << 2;
        #pragma unroll
        for (int q = 3; q >= 0; --q) {
            const int p = pbase + q;
            ulonglong2 n01 = s_n01[p];
            ulonglong2 n23 = s_n23[p];
            u64 bias = s_bias[p];
            u64 a = fma2(xq0[j], n01.x, bias);
            a = fma2(xq1[j], n01.y, a);
            a = fma2(xq2[j], n23.x, a);
            a = fma2(xq3[j], n23.y, a);
            float lo, hi; unpack2(a, lo, hi);
            if (hi == best[j]) idx = 2 * p + 1;
            if (lo == best[j]) idx = 2 * p;
        }
        bi[j] = idx;
    }

    // ---- gather chosen codewords ----
    float4 q0 = s_cw[bi[0]];
    float4 q1 = s_cw[bi[1]];
    float4 q2 = s_cw[bi[2]];
    float4 q3 = s_cw[bi[3]];

    // ql writes: row d at (h_d, w0..w0+3) = (q0[d], q1[d], q2[d], q3[d]) -> STG.128
    float* oql = out + (size_t)b * (HH * WW) + w0;
    {
        float4 r0 = make_float4(q0.x, q1.x, q2.x, q3.x);
        float4 r1 = make_float4(q0.y, q1.y, q2.y, q3.y);
        *(float4*)(oql + h0 * WW) = r0;
        *(float4*)(oql + h1 * WW) = r1;
        if (h2 < HH) {
            float4 r2 = make_float4(q0.z, q1.z, q2.z, q3.z);
            *(float4*)(oql + h2 * WW) = r2;
        }
        if (h3 < HH) {
            float4 r3 = make_float4(q0.w, q1.w, q2.w, q3.w);
            *(float4*)(oql + h3 * WW) = r3;
        }
    }

    // mse / rate partials (all 16 elements count, incl. padded duplicates)
    float lm, lr;
    {
        float d00 = q0.x - f0[0], d01 = q0.y - f1[0], d02 = q0.z - f2[0], d03 = q0.w - f3[0];
        float d10 = q1.x - f0[1], d11 = q1.y - f1[1], d12 = q1.z - f2[1], d13 = q1.w - f3[1];
        float d20 = q2.x - f0[2], d21 = q2.y - f1[2], d22 = q2.z - f2[2], d23 = q2.w - f3[2];
        float d30 = q3.x - f0[3], d31 = q3.y - f1[3], d32 = q3.z - f2[3], d33 = q3.w - f3[3];
        lm = d00*d00 + d01*d01 + d02*d02 + d03*d03
           + d10*d10 + d11*d11 + d12*d12 + d13*d13
           + d20*d20 + d21*d21 + d22*d22 + d23*d23
           + d30*d30 + d31*d31 + d32*d32 + d33*d33;
        lr = s_l2p[bi[0]] + s_l2p[bi[1]] + s_l2p[bi[2]] + s_l2p[bi[3]];
    }

    // inds: flat m = b*1024 + w*16 + c; this quarter owns [b*1024 + wq*256, +256)
    s_ind[(wl + 0) * 16 + c] = (float)bi[0];
    s_ind[(wl + 1) * 16 + c] = (float)bi[1];
    s_ind[(wl + 2) * 16 + c] = (float)bi[2];
    s_ind[(wl + 3) * 16 + c] = (float)bi[3];

    // ---- deterministic block reduction (2 warps) ----
    #pragma unroll
    for (int o = 16; o > 0; o >>= 1) {
        lm += __shfl_down_sync(0xFFFFFFFFu, lm, o);
        lr += __shfl_down_sync(0xFFFFFFFFu, lr, o);
    }
    if ((tid & 31) == 0) { s_rm[tid >> 5] = lm; s_rr[tid >> 5] = lr; }
    __syncthreads();

    // coalesced inds writeout (256 floats by 64 threads)
    float* oind = out + OFF_INDS + (size_t)b * CHUNKS_PER_B + wq * 256;
    oind[tid]       = s_ind[tid];
    oind[tid + 64]  = s_ind[tid + 64];
    oind[tid + 128] = s_ind[tid + 128];
    oind[tid + 192] = s_ind[tid + 192];

    if (tid == 0) {
        g_pmse[blk]  = s_rm[0] + s_rm[1];
        g_prate[blk] = s_rr[0] + s_rr[1];
        __threadfence();
        int v = atomicAdd(&g_count, 1);
        s_last = (v == NB4 - 1);
    }
    __syncthreads();

    // ---- fused finalize: last block reduces the 3072 partials (fixed order) ----
    if (s_last) {
        __threadfence();   // acquire: make all blocks' partials visible
        float a = 0.f, r = 0.f;
        #pragma unroll
        for (int i = 0; i < 48; ++i) {      // 3072 = 64*48, fixed order
            a += g_pmse[tid + i * 64];
            r += g_prate[tid + i * 64];
        }
        s_ind[tid]      = a;                // reuse smem
        s_ind[tid + 64] = r;
        __syncthreads();
        #pragma unroll
        for (int s = 32; s > 0; s >>= 1) {
            if (tid < s) {
                s_ind[tid]      += s_ind[tid + s];
                s_ind[64 + tid] += s_ind[64 + tid + s];
            }
            __syncthreads();
        }
        if (tid == 0) {
            out[OFF_MSE]   = s_ind[0] * (1.0f / MSE_COUNT);
            out[OFF_RATE]  = s_ind[64];
            out[OFF_PRIOR] = 0.f;
            out[OFF_PARAM] = 0.f;
            g_count = 0;   // reset for next graph replay
        }
    }
}

extern "C" void kernel_launch(void* const* d_in, const int* in_sizes, int n_in,
                              void* d_out, int out_size)
{
    const float* lat  = (const float*)d_in[0];   // latents  (4,192,62,64)
    const float* cb   = (const float*)d_in[1];   // codebook (256,4)
    const float* lpmf = (const float*)d_in[2];   // log_pmf  (256,)
    float* out = (float*)d_out;

    vq_main<<<NB4, 64>>>(lat, cb, lpmf, out);
}